// round 1
// baseline (speedup 1.0000x reference)
#include <cuda_runtime.h>

// Problem constants
#define D_MODEL   1024
#define N_HEADS   16
#define HEAD_DIM  64
#define BATCH     2
#define TQ        2048
#define TCACHE    2048
#define TKTOT     4096      // TCACHE + TQ
#define MROWS     4096      // BATCH * TQ

// Output layout (flattened pytree leaves): out [B,TQ,C], k [B,H,TKTOT,Dh], v [B,H,TKTOT,Dh]
#define OUT_ELEMS (MROWS * D_MODEL)                       // 4194304
#define KV_ELEMS  (BATCH * N_HEADS * TKTOT * HEAD_DIM)    // 8388608

// Scratch (device globals — no allocation allowed)
__device__ float g_q[BATCH * N_HEADS * TQ * HEAD_DIM];    // [b,h,t,d]
__device__ float g_att[MROWS * D_MODEL];                  // [b,t,h,d] == [4096,1024] row-major

// ---------------------------------------------------------------------------
// 1) Copy caches into the first TCACHE rows of the k/v outputs (vectorized)
// ---------------------------------------------------------------------------
__global__ void copy_cache_kernel(const float4* __restrict__ kc,
                                  const float4* __restrict__ vc,
                                  float4* __restrict__ kout,
                                  float4* __restrict__ vout) {
    int idx = blockIdx.x * blockDim.x + threadIdx.x;  // 0 .. 1048575 (float4 units)
    // per-(b,h) chunk: TCACHE*HEAD_DIM/4 = 32768 float4 src, dst stride TKTOT*HEAD_DIM/4 = 65536
    int chunk = idx >> 15;
    int off   = idx & 32767;
    int dst   = (chunk << 16) + off;
    kout[dst] = kc[idx];
    vout[dst] = vc[idx];
}

// ---------------------------------------------------------------------------
// 2) Tiled SGEMM  Y[4096,1024] = X[4096,1024] @ W[1024,1024] + bias
//    mode 0: write g_q as [b,h,t,d] (T=TQ)
//    mode 1: write dst   as [b,h,TCACHE+t,d] (T=TKTOT)  -> k/v projection rows
//    mode 2: X = g_att, write dst row-major (final out projection)
// ---------------------------------------------------------------------------
__global__ void __launch_bounds__(256) gemm_kernel(const float* __restrict__ X,
                                                   const float* __restrict__ W,
                                                   const float* __restrict__ bias,
                                                   float* __restrict__ dst, int mode) {
    __shared__ float As[16][68];   // [k][m], padded
    __shared__ float Bs[16][64];   // [k][n]

    const float* Xp = (mode == 2) ? g_att : X;
    float* dstp = (mode == 0) ? g_q : dst;

    int tid = threadIdx.x;
    int tx = tid & 15, ty = tid >> 4;
    int row0 = blockIdx.y * 64;
    int col0 = blockIdx.x * 64;

    float acc[4][4];
#pragma unroll
    for (int i = 0; i < 4; i++)
#pragma unroll
        for (int j = 0; j < 4; j++) acc[i][j] = 0.0f;

    int ar = tid >> 2;          // 0..63  (row within A tile)
    int ac = (tid & 3) << 2;    // 0,4,8,12 (k within A tile)
    int br = tid >> 4;          // 0..15  (k within B tile)
    int bc = (tid & 15) << 2;   // 0..60  (col within B tile)

    for (int k0 = 0; k0 < D_MODEL; k0 += 16) {
        float4 av = *(const float4*)&Xp[(row0 + ar) * D_MODEL + k0 + ac];
        As[ac + 0][ar] = av.x;
        As[ac + 1][ar] = av.y;
        As[ac + 2][ar] = av.z;
        As[ac + 3][ar] = av.w;
        *(float4*)&Bs[br][bc] = *(const float4*)&W[(k0 + br) * D_MODEL + col0 + bc];
        __syncthreads();
#pragma unroll
        for (int kk = 0; kk < 16; kk++) {
            float4 a = *(const float4*)&As[kk][ty << 2];
            float4 b = *(const float4*)&Bs[kk][tx << 2];
            acc[0][0] += a.x * b.x; acc[0][1] += a.x * b.y; acc[0][2] += a.x * b.z; acc[0][3] += a.x * b.w;
            acc[1][0] += a.y * b.x; acc[1][1] += a.y * b.y; acc[1][2] += a.y * b.z; acc[1][3] += a.y * b.w;
            acc[2][0] += a.z * b.x; acc[2][1] += a.z * b.y; acc[2][2] += a.z * b.z; acc[2][3] += a.z * b.w;
            acc[3][0] += a.w * b.x; acc[3][1] += a.w * b.y; acc[3][2] += a.w * b.z; acc[3][3] += a.w * b.w;
        }
        __syncthreads();
    }

#pragma unroll
    for (int i = 0; i < 4; i++) {
        int r = row0 + (ty << 2) + i;
        int b = r >> 11;         // / TQ
        int t = r & 2047;
#pragma unroll
        for (int j = 0; j < 4; j++) {
            int c = col0 + (tx << 2) + j;
            float val = acc[i][j] + bias[c];
            int idx;
            if (mode == 2) {
                idx = r * D_MODEL + c;
            } else {
                int h = c >> 6, d = c & 63;
                if (mode == 0)
                    idx = (((b * N_HEADS + h) * TQ) + t) * HEAD_DIM + d;
                else
                    idx = (((b * N_HEADS + h) * TKTOT) + TCACHE + t) * HEAD_DIM + d;
            }
            dstp[idx] = val;
        }
    }
}

// ---------------------------------------------------------------------------
// 3) Flash attention (fp32, online softmax).
//    Grid: (32 q-tiles, 32 b*h). Block: 256 threads = 8 warps.
//    Warp w owns q-rows [8w, 8w+8); lane owns output cols {2*lane, 2*lane+1}.
// ---------------------------------------------------------------------------
#define ATTN_SMEM_FLOATS (4096 + 64 * 66 + 4096 + 4096)   // Qs, Ksh(padded), Vsh, Ps
#define ATTN_SMEM_BYTES  (ATTN_SMEM_FLOATS * 4)

__global__ void __launch_bounds__(256) attn_kernel(const float* __restrict__ Kg,
                                                   const float* __restrict__ Vg) {
    extern __shared__ float smem[];
    float* Qs  = smem;                    // [64][64] row-major [r][d]
    float* Ksh = smem + 4096;             // [64][66]            [d][j] (transposed, padded)
    float* Vsh = Ksh + 64 * 66;           // [64][64]            [j][c]
    float* Ps  = Vsh + 4096;              // [64][64]            [r][j]

    int tid  = threadIdx.x;
    int lane = tid & 31, w = tid >> 5;
    int qt = blockIdx.x;                  // q tile 0..31
    int bh = blockIdx.y;                  // 0..31
    int i0 = qt << 6;
    int r0 = w << 3;

    const float* Qg = g_q + bh * (TQ * HEAD_DIM);
    const float* Kb = Kg + bh * (TKTOT * HEAD_DIM);
    const float* Vb = Vg + bh * (TKTOT * HEAD_DIM);

    // Load Q tile (64x64)
#pragma unroll
    for (int it = 0; it < 4; it++) {
        int fid = it * 256 + tid;        // float4 index 0..1023
        int r = fid >> 4, dg = (fid & 15) << 2;
        *(float4*)&Qs[r * 64 + dg] = *(const float4*)&Qg[(i0 + r) * 64 + dg];
    }

    float O[8][2], m[8], l[8];
#pragma unroll
    for (int i = 0; i < 8; i++) { m[i] = -1e30f; l[i] = 0.0f; O[i][0] = 0.0f; O[i][1] = 0.0f; }

    int ntiles = qt + 33;                // last allowed key index is i0+63+TCACHE
    for (int kt = 0; kt < ntiles; kt++) {
        int j0 = kt << 6;
        __syncthreads();                 // protect Ksh/Vsh/Ps from prev-iter readers
        // Load K (transposed) and V tiles
#pragma unroll
        for (int it = 0; it < 4; it++) {
            int fid = it * 256 + tid;
            int jj = fid >> 4, dg = (fid & 15) << 2;
            float4 kv = *(const float4*)&Kb[(j0 + jj) * 64 + dg];
            Ksh[(dg + 0) * 66 + jj] = kv.x;
            Ksh[(dg + 1) * 66 + jj] = kv.y;
            Ksh[(dg + 2) * 66 + jj] = kv.z;
            Ksh[(dg + 3) * 66 + jj] = kv.w;
            *(float4*)&Vsh[jj * 64 + dg] = *(const float4*)&Vb[(j0 + jj) * 64 + dg];
        }
        __syncthreads();

        // Scores: S[8 rows][2 cols per lane]
        float S[8][2];
#pragma unroll
        for (int i = 0; i < 8; i++) { S[i][0] = 0.0f; S[i][1] = 0.0f; }
#pragma unroll
        for (int kk4 = 0; kk4 < 64; kk4 += 4) {
            float2 kc[4];
#pragma unroll
            for (int u = 0; u < 4; u++)
                kc[u] = *(const float2*)&Ksh[(kk4 + u) * 66 + (lane << 1)];
#pragma unroll
            for (int rr = 0; rr < 8; rr++) {
                float4 q = *(const float4*)&Qs[(r0 + rr) * 64 + kk4];
                S[rr][0] += q.x * kc[0].x + q.y * kc[1].x + q.z * kc[2].x + q.w * kc[3].x;
                S[rr][1] += q.x * kc[0].y + q.y * kc[1].y + q.z * kc[2].y + q.w * kc[3].y;
            }
        }

        const float scale = 0.125f;      // 1/sqrt(64)
        bool maskTile = (kt == qt + 32);
#pragma unroll
        for (int rr = 0; rr < 8; rr++) {
            float s0 = S[rr][0] * scale;
            float s1 = S[rr][1] * scale;
            if (maskTile) {
                int ilim = i0 + r0 + rr + TCACHE;   // max allowed key index
                int j = j0 + (lane << 1);
                if (j > ilim)     s0 = -1e30f;
                if (j + 1 > ilim) s1 = -1e30f;
            }
            float mx = fmaxf(s0, s1);
#pragma unroll
            for (int o = 16; o > 0; o >>= 1)
                mx = fmaxf(mx, __shfl_xor_sync(0xffffffffu, mx, o));
            float mnew = fmaxf(m[rr], mx);
            float alpha = __expf(m[rr] - mnew);
            float p0 = __expf(s0 - mnew);
            float p1 = __expf(s1 - mnew);
            float ps = p0 + p1;
#pragma unroll
            for (int o = 16; o > 0; o >>= 1)
                ps += __shfl_xor_sync(0xffffffffu, ps, o);
            l[rr] = l[rr] * alpha + ps;
            m[rr] = mnew;
            O[rr][0] *= alpha;
            O[rr][1] *= alpha;
            *(float2*)&Ps[(r0 + rr) * 64 + (lane << 1)] = make_float2(p0, p1);
        }
        __syncwarp();                    // Ps rows are per-warp private

        // O += P @ V
#pragma unroll
        for (int j4 = 0; j4 < 64; j4 += 4) {
            float2 vv[4];
#pragma unroll
            for (int u = 0; u < 4; u++)
                vv[u] = *(const float2*)&Vsh[(j4 + u) * 64 + (lane << 1)];
#pragma unroll
            for (int rr = 0; rr < 8; rr++) {
                float4 p = *(const float4*)&Ps[(r0 + rr) * 64 + j4];
                O[rr][0] += p.x * vv[0].x + p.y * vv[1].x + p.z * vv[2].x + p.w * vv[3].x;
                O[rr][1] += p.x * vv[0].y + p.y * vv[1].y + p.z * vv[2].y + p.w * vv[3].y;
            }
        }
    }

    // Epilogue: normalize and write [b,t,h,d]
    int b = bh >> 4, h = bh & 15;
#pragma unroll
    for (int rr = 0; rr < 8; rr++) {
        float inv = 1.0f / l[rr];
        int t = i0 + r0 + rr;
        int base = ((b * TQ + t) * N_HEADS + h) * HEAD_DIM + (lane << 1);
        g_att[base]     = O[rr][0] * inv;
        g_att[base + 1] = O[rr][1] * inv;
    }
}

// ---------------------------------------------------------------------------
extern "C" void kernel_launch(void* const* d_in, const int* in_sizes, int n_in,
                              void* d_out, int out_size) {
    (void)in_sizes; (void)n_in; (void)out_size;
    const float* x  = (const float*)d_in[0];
    const float* kc = (const float*)d_in[1];
    const float* vc = (const float*)d_in[2];
    const float* Wq = (const float*)d_in[3];
    const float* bq = (const float*)d_in[4];
    const float* Wk = (const float*)d_in[5];
    const float* bk = (const float*)d_in[6];
    const float* Wv = (const float*)d_in[7];
    const float* bv = (const float*)d_in[8];
    const float* Wo = (const float*)d_in[9];
    const float* bo = (const float*)d_in[10];

    float* out   = (float*)d_out;
    float* k_out = out + OUT_ELEMS;
    float* v_out = k_out + KV_ELEMS;

    // 1) copy caches (k/v rows [0, TCACHE))
    copy_cache_kernel<<<4096, 256>>>((const float4*)kc, (const float4*)vc,
                                     (float4*)k_out, (float4*)v_out);

    // 2) projections
    dim3 ggrid(D_MODEL / 64, MROWS / 64);   // (16, 64)
    gemm_kernel<<<ggrid, 256>>>(x, Wq, bq, nullptr, 0);   // -> g_q
    gemm_kernel<<<ggrid, 256>>>(x, Wk, bk, k_out, 1);     // -> k_out rows [TCACHE, TKTOT)
    gemm_kernel<<<ggrid, 256>>>(x, Wv, bv, v_out, 1);     // -> v_out rows [TCACHE, TKTOT)

    // 3) flash attention -> g_att
    cudaFuncSetAttribute(attn_kernel, cudaFuncAttributeMaxDynamicSharedMemorySize,
                         ATTN_SMEM_BYTES);
    attn_kernel<<<dim3(TQ / 64, BATCH * N_HEADS), 256, ATTN_SMEM_BYTES>>>(k_out, v_out);

    // 4) output projection -> out
    gemm_kernel<<<ggrid, 256>>>(nullptr, Wo, bo, out, 2);
}

// round 5
// speedup vs baseline: 1.1170x; 1.1170x over previous
#include <cuda_runtime.h>

// Problem constants
#define D_MODEL   1024
#define N_HEADS   16
#define HEAD_DIM  64
#define BATCH     2
#define TQ        2048
#define TCACHE    2048
#define TKTOT     4096
#define MROWS     4096

#define OUT_ELEMS (MROWS * D_MODEL)
#define KV_ELEMS  (BATCH * N_HEADS * TKTOT * HEAD_DIM)

// Scratch (device globals — no allocation allowed)
__device__ float g_q[BATCH * N_HEADS * TQ * HEAD_DIM];    // [b,h,t,d]
__device__ float g_att[MROWS * D_MODEL];                  // [b,t,h,d] row-major [4096,1024]

// ---------------------------------------------------------------------------
// 1) Cache copy (k/v rows [0, TCACHE))
// ---------------------------------------------------------------------------
__global__ void copy_cache_kernel(const float4* __restrict__ kc,
                                  const float4* __restrict__ vc,
                                  float4* __restrict__ kout,
                                  float4* __restrict__ vout) {
    int idx = blockIdx.x * blockDim.x + threadIdx.x;  // 0 .. 1048575
    int chunk = idx >> 15;            // (b,h) chunk
    int off   = idx & 32767;
    int dst   = (chunk << 16) + off;  // dst stride TKTOT*HEAD_DIM/4 = 65536
    kout[dst] = kc[idx];
    vout[dst] = vc[idx];
}

// ---------------------------------------------------------------------------
// 2) SGEMM core: 128x128 tile, BK=8, 256 threads, 8x8 micro-tile, prefetch.
//    MODE 0: dst = g_q [b,h,t,d] (T=TQ)
//    MODE 1: dst = k/v out, rows [TCACHE, TKTOT)
//    MODE 2: dst row-major [4096,1024]
// ---------------------------------------------------------------------------
template<int MODE>
__device__ __forceinline__ void gemm_core(const float* __restrict__ X,
                                          const float* __restrict__ W,
                                          const float* __restrict__ bias,
                                          float* __restrict__ dst,
                                          float* As, float* Bs) {
    const int tid = threadIdx.x;
    const int tx = tid & 15, ty = tid >> 4;
    const int row0 = blockIdx.y * 128, col0 = blockIdx.x * 128;

    float acc[8][8];
#pragma unroll
    for (int i = 0; i < 8; i++)
#pragma unroll
        for (int j = 0; j < 8; j++) acc[i][j] = 0.0f;

    const int arow = tid >> 1, acol = (tid & 1) << 2;
    const int brow = tid >> 5, bcol = (tid & 31) << 2;
    const float* Xp = X + (size_t)(row0 + arow) * D_MODEL + acol;
    const float* Wp = W + (size_t)brow * D_MODEL + col0 + bcol;

    float4 av = *(const float4*)Xp;
    float4 bv = *(const float4*)Wp;

    for (int k0 = 0; k0 < D_MODEL; k0 += 8) {
        As[(acol + 0) * 132 + arow] = av.x;
        As[(acol + 1) * 132 + arow] = av.y;
        As[(acol + 2) * 132 + arow] = av.z;
        As[(acol + 3) * 132 + arow] = av.w;
        *(float4*)&Bs[brow * 128 + bcol] = bv;
        __syncthreads();
        if (k0 + 8 < D_MODEL) {                       // prefetch next slab
            av = *(const float4*)(Xp + k0 + 8);
            bv = *(const float4*)(Wp + (size_t)(k0 + 8) * D_MODEL);
        }
#pragma unroll
        for (int kk = 0; kk < 8; kk++) {
            float4 a0 = *(const float4*)&As[kk * 132 + ty * 8];
            float4 a1 = *(const float4*)&As[kk * 132 + ty * 8 + 4];
            float4 b0 = *(const float4*)&Bs[kk * 128 + tx * 8];
            float4 b1 = *(const float4*)&Bs[kk * 128 + tx * 8 + 4];
            float aa[8] = {a0.x, a0.y, a0.z, a0.w, a1.x, a1.y, a1.z, a1.w};
            float bb[8] = {b0.x, b0.y, b0.z, b0.w, b1.x, b1.y, b1.z, b1.w};
#pragma unroll
            for (int i = 0; i < 8; i++)
#pragma unroll
                for (int j = 0; j < 8; j++) acc[i][j] += aa[i] * bb[j];
        }
        __syncthreads();
    }

    // Epilogue: bias + scatter, float4 stores
#pragma unroll
    for (int jg = 0; jg < 2; jg++) {
        int c0 = col0 + tx * 8 + jg * 4;
        float4 b4 = *(const float4*)&bias[c0];
        int h = c0 >> 6, d = c0 & 63;
#pragma unroll
        for (int i = 0; i < 8; i++) {
            int r = row0 + ty * 8 + i;
            float4 o;
            o.x = acc[i][jg * 4 + 0] + b4.x;
            o.y = acc[i][jg * 4 + 1] + b4.y;
            o.z = acc[i][jg * 4 + 2] + b4.z;
            o.w = acc[i][jg * 4 + 3] + b4.w;
            size_t idx;
            if (MODE == 2) {
                idx = (size_t)r * D_MODEL + c0;
            } else {
                int b = r >> 11, t = r & 2047;
                if (MODE == 0)
                    idx = ((size_t)(b * N_HEADS + h) * TQ + t) * HEAD_DIM + d;
                else
                    idx = ((size_t)(b * N_HEADS + h) * TKTOT + TCACHE + t) * HEAD_DIM + d;
            }
            *(float4*)&dst[idx] = o;
        }
    }
}

__global__ void __launch_bounds__(256, 2) qkv_kernel(
        const float* __restrict__ x,
        const float* __restrict__ Wq, const float* __restrict__ bq,
        const float* __restrict__ Wk, const float* __restrict__ bk,
        const float* __restrict__ Wv, const float* __restrict__ bv,
        float* __restrict__ kout, float* __restrict__ vout) {
    __shared__ float As[8 * 132];
    __shared__ float Bs[8 * 128];
    int z = blockIdx.z;
    if (z == 0)      gemm_core<0>(x, Wq, bq, g_q,  As, Bs);
    else if (z == 1) gemm_core<1>(x, Wk, bk, kout, As, Bs);
    else             gemm_core<1>(x, Wv, bv, vout, As, Bs);
}

__global__ void __launch_bounds__(256, 2) oproj_kernel(
        const float* __restrict__ Wo, const float* __restrict__ bo,
        float* __restrict__ out) {
    __shared__ float As[8 * 132];
    __shared__ float Bs[8 * 128];
    gemm_core<2>(g_att, Wo, bo, out, As, Bs);
}

// ---------------------------------------------------------------------------
// 3) Flash attention: Q-tile 128 x K-tile 64, 256 threads, 8x4 micro-tile.
//    Smem layouts: Qt[d][r] pitch 132, Ks[d][j] pitch 68, Vs[j][c] pitch 68,
//    Ps[r][j] pitch 68. All inner-loop reads are broadcasts or clean float4s.
// ---------------------------------------------------------------------------
#define AT_SMEM_FLOATS (64 * 132 + 64 * 68 + 64 * 68 + 128 * 68)
#define AT_SMEM_BYTES  (AT_SMEM_FLOATS * 4)

__global__ void __launch_bounds__(256, 2) attn_kernel(const float* __restrict__ Kg,
                                                      const float* __restrict__ Vg) {
    extern __shared__ float sm[];
    float* Qt = sm;                    // [64][132]  Qt[d][r]
    float* Ks = Qt + 64 * 132;         // [64][68]   Ks[d][j]
    float* Vs = Ks + 64 * 68;          // [64][68]   Vs[j][c]
    float* Ps = Vs + 64 * 68;          // [128][68]  Ps[r][j]

    const int tid = threadIdx.x;
    const int tx = tid & 15, ty = tid >> 4;
    const int qt = blockIdx.x, bh = blockIdx.y;
    const int i0 = qt << 7;
    const int r_base = ty << 3;        // rows r_base..r_base+7
    const int cx = tx << 2;            // cols cx..cx+3

    const float* Qg = g_q + (size_t)bh * (TQ * HEAD_DIM);
    const float* Kb = Kg + (size_t)bh * (TKTOT * HEAD_DIM);
    const float* Vb = Vg + (size_t)bh * (TKTOT * HEAD_DIM);

    // Load Q tile 128x64 -> Qt[d][r]
#pragma unroll
    for (int it = 0; it < 8; it++) {
        int fid = it * 256 + tid;
        int r = fid >> 4, dg = (fid & 15) << 2;
        float4 q = *(const float4*)&Qg[(size_t)(i0 + r) * 64 + dg];
        Qt[(dg + 0) * 132 + r] = q.x;
        Qt[(dg + 1) * 132 + r] = q.y;
        Qt[(dg + 2) * 132 + r] = q.z;
        Qt[(dg + 3) * 132 + r] = q.w;
    }

    float O[8][4];
    float m[8], l[8];
#pragma unroll
    for (int i = 0; i < 8; i++) {
        m[i] = -1e30f; l[i] = 0.0f;
        O[i][0] = O[i][1] = O[i][2] = O[i][3] = 0.0f;
    }

    const int ntiles = 2 * qt + 34;
    const int mask_start = 2 * qt + 32;

    for (int kt = 0; kt < ntiles; kt++) {
        int j0 = kt << 6;
        __syncthreads();               // prev-iter readers of Ks/Vs done
#pragma unroll
        for (int it = 0; it < 4; it++) {
            int fid = it * 256 + tid;
            int jj = fid >> 4, dg = (fid & 15) << 2;
            float4 kv = *(const float4*)&Kb[(size_t)(j0 + jj) * 64 + dg];
            Ks[(dg + 0) * 68 + jj] = kv.x;
            Ks[(dg + 1) * 68 + jj] = kv.y;
            Ks[(dg + 2) * 68 + jj] = kv.z;
            Ks[(dg + 3) * 68 + jj] = kv.w;
            float4 vv = *(const float4*)&Vb[(size_t)(j0 + jj) * 64 + dg];
            *(float4*)&Vs[jj * 68 + dg] = vv;
        }
        __syncthreads();

        // S = Q K^T  (8 rows x 4 cols per thread)
        float S[8][4];
#pragma unroll
        for (int i = 0; i < 8; i++) { S[i][0] = S[i][1] = S[i][2] = S[i][3] = 0.0f; }
#pragma unroll 8
        for (int kk = 0; kk < 64; kk++) {
            float4 q0 = *(const float4*)&Qt[kk * 132 + r_base];
            float4 q1 = *(const float4*)&Qt[kk * 132 + r_base + 4];
            float4 kv = *(const float4*)&Ks[kk * 68 + cx];
            float qa[8] = {q0.x, q0.y, q0.z, q0.w, q1.x, q1.y, q1.z, q1.w};
            float kb[4] = {kv.x, kv.y, kv.z, kv.w};
#pragma unroll
            for (int i = 0; i < 8; i++)
#pragma unroll
                for (int j = 0; j < 4; j++) S[i][j] += qa[i] * kb[j];
        }

        // online softmax per row (row owners = 16 lanes sharing ty -> half-warp)
        const bool bmask = (kt >= mask_start);
#pragma unroll
        for (int i = 0; i < 8; i++) {
            float s0 = S[i][0] * 0.125f;
            float s1 = S[i][1] * 0.125f;
            float s2 = S[i][2] * 0.125f;
            float s3 = S[i][3] * 0.125f;
            if (bmask) {
                int jlim = i0 + r_base + i + TCACHE;
                int jc = j0 + cx;
                if (jc + 0 > jlim) s0 = -1e30f;
                if (jc + 1 > jlim) s1 = -1e30f;
                if (jc + 2 > jlim) s2 = -1e30f;
                if (jc + 3 > jlim) s3 = -1e30f;
            }
            float mx = fmaxf(fmaxf(s0, s1), fmaxf(s2, s3));
#pragma unroll
            for (int o = 8; o > 0; o >>= 1)
                mx = fmaxf(mx, __shfl_xor_sync(0xffffffffu, mx, o));
            float mnew = fmaxf(m[i], mx);
            float alpha = __expf(m[i] - mnew);
            float p0 = __expf(s0 - mnew);
            float p1 = __expf(s1 - mnew);
            float p2 = __expf(s2 - mnew);
            float p3 = __expf(s3 - mnew);
            float ps = (p0 + p1) + (p2 + p3);
#pragma unroll
            for (int o = 8; o > 0; o >>= 1)
                ps += __shfl_xor_sync(0xffffffffu, ps, o);
            l[i] = l[i] * alpha + ps;
            m[i] = mnew;
            O[i][0] *= alpha; O[i][1] *= alpha; O[i][2] *= alpha; O[i][3] *= alpha;
            *(float4*)&Ps[(r_base + i) * 68 + cx] = make_float4(p0, p1, p2, p3);
        }
        __syncwarp();                  // Ps rows produced+consumed within half-warp

        // O += P V   (inner dim j, unrolled by 4)
#pragma unroll 4
        for (int jj = 0; jj < 64; jj += 4) {
            float4 vv0 = *(const float4*)&Vs[(jj + 0) * 68 + cx];
            float4 vv1 = *(const float4*)&Vs[(jj + 1) * 68 + cx];
            float4 vv2 = *(const float4*)&Vs[(jj + 2) * 68 + cx];
            float4 vv3 = *(const float4*)&Vs[(jj + 3) * 68 + cx];
#pragma unroll
            for (int i = 0; i < 8; i++) {
                float4 p = *(const float4*)&Ps[(r_base + i) * 68 + jj];
                O[i][0] += p.x * vv0.x + p.y * vv1.x + p.z * vv2.x + p.w * vv3.x;
                O[i][1] += p.x * vv0.y + p.y * vv1.y + p.z * vv2.y + p.w * vv3.y;
                O[i][2] += p.x * vv0.z + p.y * vv1.z + p.z * vv2.z + p.w * vv3.z;
                O[i][3] += p.x * vv0.w + p.y * vv1.w + p.z * vv2.w + p.w * vv3.w;
            }
        }
    }

    // Epilogue: normalize + write g_att [b,t,h,d]
    int b = bh >> 4, h = bh & 15;
#pragma unroll
    for (int i = 0; i < 8; i++) {
        float inv = 1.0f / l[i];
        int t = i0 + r_base + i;
        float4 o = make_float4(O[i][0] * inv, O[i][1] * inv, O[i][2] * inv, O[i][3] * inv);
        *(float4*)&g_att[((size_t)(b * TQ + t) * N_HEADS + h) * HEAD_DIM + cx] = o;
    }
}

// ---------------------------------------------------------------------------
extern "C" void kernel_launch(void* const* d_in, const int* in_sizes, int n_in,
                              void* d_out, int out_size) {
    (void)in_sizes; (void)n_in; (void)out_size;
    const float* x  = (const float*)d_in[0];
    const float* kc = (const float*)d_in[1];
    const float* vc = (const float*)d_in[2];
    const float* Wq = (const float*)d_in[3];
    const float* bq = (const float*)d_in[4];
    const float* Wk = (const float*)d_in[5];
    const float* bk = (const float*)d_in[6];
    const float* Wv = (const float*)d_in[7];
    const float* bv = (const float*)d_in[8];
    const float* Wo = (const float*)d_in[9];
    const float* bo = (const float*)d_in[10];

    float* out   = (float*)d_out;
    float* k_out = out + OUT_ELEMS;
    float* v_out = k_out + KV_ELEMS;

    copy_cache_kernel<<<4096, 256>>>((const float4*)kc, (const float4*)vc,
                                     (float4*)k_out, (float4*)v_out);

    // Fused QKV projections: grid (8 col-tiles, 32 row-tiles, 3 matrices)
    qkv_kernel<<<dim3(8, 32, 3), 256>>>(x, Wq, bq, Wk, bk, Wv, bv, k_out, v_out);

    // Flash attention
    cudaFuncSetAttribute(attn_kernel, cudaFuncAttributeMaxDynamicSharedMemorySize,
                         AT_SMEM_BYTES);
    attn_kernel<<<dim3(TQ / 128, BATCH * N_HEADS), 256, AT_SMEM_BYTES>>>(k_out, v_out);

    // Output projection
    oproj_kernel<<<dim3(8, 32), 256>>>(Wo, bo, out);
}

// round 6
// speedup vs baseline: 3.2945x; 2.9493x over previous
#include <cuda_runtime.h>
#include <cstdint>

// Problem constants
#define D_MODEL   1024
#define N_HEADS   16
#define HEAD_DIM  64
#define BATCH     2
#define TQ        2048
#define TCACHE    2048
#define TKTOT     4096
#define MROWS     4096

#define OUT_ELEMS (MROWS * D_MODEL)
#define KV_ELEMS  (BATCH * N_HEADS * TKTOT * HEAD_DIM)

// Scratch (device globals — no allocation allowed)
__device__ float g_q[BATCH * N_HEADS * TQ * HEAD_DIM];    // [b,h,t,d], pre-scaled by 1/8 in tf32? no: raw fp32
__device__ float g_att[MROWS * D_MODEL];                  // [b,t,h,d] row-major [4096,1024]

// ---------------------------------------------------------------------------
// helpers: tf32 convert + m16n8k8 tf32 MMA
// ---------------------------------------------------------------------------
__device__ __forceinline__ unsigned f2tf(float x) {
    unsigned u;
    asm("cvt.rna.tf32.f32 %0, %1;" : "=r"(u) : "f"(x));
    return u;
}

__device__ __forceinline__ void mma8(float* c, const unsigned* a, unsigned b0, unsigned b1) {
    asm volatile(
        "mma.sync.aligned.m16n8k8.row.col.f32.tf32.tf32.f32 "
        "{%0,%1,%2,%3}, {%4,%5,%6,%7}, {%8,%9}, {%0,%1,%2,%3};\n"
        : "+f"(c[0]), "+f"(c[1]), "+f"(c[2]), "+f"(c[3])
        : "r"(a[0]), "r"(a[1]), "r"(a[2]), "r"(a[3]), "r"(b0), "r"(b1));
}

// ---------------------------------------------------------------------------
// 1) Cache copy (k/v rows [0, TCACHE))
// ---------------------------------------------------------------------------
__global__ void copy_cache_kernel(const float4* __restrict__ kc,
                                  const float4* __restrict__ vc,
                                  float4* __restrict__ kout,
                                  float4* __restrict__ vout) {
    int idx = blockIdx.x * blockDim.x + threadIdx.x;  // 0 .. 1048575
    int chunk = idx >> 15;
    int off   = idx & 32767;
    int dst   = (chunk << 16) + off;
    kout[dst] = kc[idx];
    vout[dst] = vc[idx];
}

// ---------------------------------------------------------------------------
// 2) TF32 GEMM: Y[4096,1024] = X[4096,1024] @ W[1024,1024] + bias
//    CTA tile 128x128, BK=16, 256 thr = 8 warps, warp tile 64x32.
//    Smem: As [m][k] pitch 20 (u32/tf32), Bs [k][n] pitch 136. Both pitches
//    give conflict-free fragment gathers (20*g mod 32 and 136*t mod 32 spread).
//    MODE 0: dst = g_q [b,h,t,d]; MODE 1: k/v rows [TCACHE,TKTOT); MODE 2: row-major
// ---------------------------------------------------------------------------
template<int MODE>
__device__ __forceinline__ void gemm_core(const float* __restrict__ X,
                                          const float* __restrict__ W,
                                          const float* __restrict__ bias,
                                          float* __restrict__ dst,
                                          unsigned* As, unsigned* Bs) {
    const int tid = threadIdx.x;
    const int lane = tid & 31, w = tid >> 5;
    const int gi = lane >> 2, ti = lane & 3;
    const int wm = w & 1, wn = w >> 1;          // warp tile: rows wm*64, cols wn*32
    const int row0 = blockIdx.y * 128, col0 = blockIdx.x * 128;

    float acc[4][4][4] = {};

    const int xr = tid >> 1, xk = (tid & 1) * 8;
    const int wk = tid >> 4, wn0 = (tid & 15) * 8;
    const float* Xp = X + (size_t)(row0 + xr) * D_MODEL + xk;
    const float* Wp = W + (size_t)wk * D_MODEL + col0 + wn0;

    float4 xa = *(const float4*)Xp;
    float4 xb = *(const float4*)(Xp + 4);
    float4 wa = *(const float4*)Wp;
    float4 wb = *(const float4*)(Wp + 4);

    for (int k0 = 0; k0 < D_MODEL; k0 += 16) {
        *(uint4*)&As[xr * 20 + xk]     = make_uint4(f2tf(xa.x), f2tf(xa.y), f2tf(xa.z), f2tf(xa.w));
        *(uint4*)&As[xr * 20 + xk + 4] = make_uint4(f2tf(xb.x), f2tf(xb.y), f2tf(xb.z), f2tf(xb.w));
        *(uint4*)&Bs[wk * 136 + wn0]     = make_uint4(f2tf(wa.x), f2tf(wa.y), f2tf(wa.z), f2tf(wa.w));
        *(uint4*)&Bs[wk * 136 + wn0 + 4] = make_uint4(f2tf(wb.x), f2tf(wb.y), f2tf(wb.z), f2tf(wb.w));
        __syncthreads();
        if (k0 + 16 < D_MODEL) {
            xa = *(const float4*)(Xp + k0 + 16);
            xb = *(const float4*)(Xp + k0 + 20);
            wa = *(const float4*)(Wp + (size_t)(k0 + 16) * D_MODEL);
            wb = *(const float4*)(Wp + (size_t)(k0 + 16) * D_MODEL + 4);
        }
#pragma unroll
        for (int ks = 0; ks < 2; ks++) {
            unsigned af[4][4];
#pragma unroll
            for (int mt = 0; mt < 4; mt++) {
                int rb = wm * 64 + mt * 16;
                af[mt][0] = As[(rb + gi)     * 20 + ks * 8 + ti];
                af[mt][1] = As[(rb + gi + 8) * 20 + ks * 8 + ti];
                af[mt][2] = As[(rb + gi)     * 20 + ks * 8 + ti + 4];
                af[mt][3] = As[(rb + gi + 8) * 20 + ks * 8 + ti + 4];
            }
#pragma unroll
            for (int nt = 0; nt < 4; nt++) {
                int cb = wn * 32 + nt * 8;
                unsigned b0 = Bs[(ks * 8 + ti)     * 136 + cb + gi];
                unsigned b1 = Bs[(ks * 8 + ti + 4) * 136 + cb + gi];
#pragma unroll
                for (int mt = 0; mt < 4; mt++) mma8(acc[mt][nt], af[mt], b0, b1);
            }
        }
        __syncthreads();
    }

    // Epilogue: bias + scatter (float2 granularity)
#pragma unroll
    for (int mt = 0; mt < 4; mt++) {
#pragma unroll
        for (int nt = 0; nt < 4; nt++) {
            int row = row0 + wm * 64 + mt * 16 + gi;
            int col = col0 + wn * 32 + nt * 8 + 2 * ti;
            float2 bb = *(const float2*)&bias[col];
            float2 v0 = make_float2(acc[mt][nt][0] + bb.x, acc[mt][nt][1] + bb.y);
            float2 v1 = make_float2(acc[mt][nt][2] + bb.x, acc[mt][nt][3] + bb.y);
#pragma unroll
            for (int p = 0; p < 2; p++) {
                int r = row + p * 8;
                float2 v = p ? v1 : v0;
                size_t idx;
                if (MODE == 2) {
                    idx = (size_t)r * D_MODEL + col;
                } else {
                    int b = r >> 11, t = r & 2047;
                    int h = col >> 6, d = col & 63;
                    if (MODE == 0)
                        idx = ((size_t)(b * N_HEADS + h) * TQ + t) * HEAD_DIM + d;
                    else
                        idx = ((size_t)(b * N_HEADS + h) * TKTOT + TCACHE + t) * HEAD_DIM + d;
                }
                *(float2*)&dst[idx] = v;
            }
        }
    }
}

__global__ void __launch_bounds__(256, 2) qkv_kernel(
        const float* __restrict__ x,
        const float* __restrict__ Wq, const float* __restrict__ bq,
        const float* __restrict__ Wk, const float* __restrict__ bk,
        const float* __restrict__ Wv, const float* __restrict__ bv,
        float* __restrict__ kout, float* __restrict__ vout) {
    __shared__ unsigned As[128 * 20];
    __shared__ unsigned Bs[16 * 136];
    int z = blockIdx.z;
    if (z == 0)      gemm_core<0>(x, Wq, bq, g_q,  As, Bs);
    else if (z == 1) gemm_core<1>(x, Wk, bk, kout, As, Bs);
    else             gemm_core<1>(x, Wv, bv, vout, As, Bs);
}

__global__ void __launch_bounds__(256, 2) oproj_kernel(
        const float* __restrict__ Wo, const float* __restrict__ bo,
        float* __restrict__ out) {
    __shared__ unsigned As[128 * 20];
    __shared__ unsigned Bs[16 * 136];
    gemm_core<2>(g_att, Wo, bo, out, As, Bs);
}

// ---------------------------------------------------------------------------
// 3) Flash attention, tensor-core TF32.
//    CTA: 128 q-rows x (b,h); 128 threads = 4 warps, warp = 32 q-rows.
//    K-tile 64 keys. S and PV via mma.m16n8k8.tf32; softmax on fragments
//    with quad-lane reductions. Smem (u32/tf32 payloads):
//      Qs [128][68], Ps [128][68]  (A-operand pitch: 68*g mod 32 spread)
//      Ks [64][68]  (j-rows; B-operand n-indexed rows -> pitch 68 ok)
//      Vs [64][72]  (j-rows; B-operand k-indexed rows -> pitch 72)
// ---------------------------------------------------------------------------
#define AT_SMEM_U32   (128 * 68 + 128 * 68 + 64 * 68 + 64 * 72)
#define AT_SMEM_BYTES (AT_SMEM_U32 * 4)

__global__ void __launch_bounds__(128, 2) attn_kernel(const float* __restrict__ Kg,
                                                      const float* __restrict__ Vg) {
    extern __shared__ unsigned smu[];
    unsigned* Qs = smu;                    // [128][68]
    unsigned* Ps = Qs + 128 * 68;          // [128][68]
    unsigned* Ks = Ps + 128 * 68;          // [64][68]
    unsigned* Vs = Ks + 64 * 68;           // [64][72]

    const int tid = threadIdx.x;
    const int lane = tid & 31, w = tid >> 5;
    const int gi = lane >> 2, ti = lane & 3;
    const int qt = (int)gridDim.x - 1 - (int)blockIdx.x;   // big tiles first
    const int bh = blockIdx.y;
    const int i0 = qt << 7;
    const int rbw = w * 32;                // warp's q-row base within tile

    const float* Qg = g_q + (size_t)bh * (TQ * HEAD_DIM);
    const float* Kb = Kg + (size_t)bh * (TKTOT * HEAD_DIM);
    const float* Vb = Vg + (size_t)bh * (TKTOT * HEAD_DIM);

    // Load Q tile (pre-scaled by 1/sqrt(64)=0.125, converted to tf32)
#pragma unroll
    for (int it = 0; it < 16; it++) {
        int fid = it * 128 + tid;          // float4 index 0..2047
        int r = fid >> 4, d0 = (fid & 15) << 2;
        float4 q = *(const float4*)&Qg[(size_t)(i0 + r) * 64 + d0];
        *(uint4*)&Qs[r * 68 + d0] = make_uint4(f2tf(q.x * 0.125f), f2tf(q.y * 0.125f),
                                               f2tf(q.z * 0.125f), f2tf(q.w * 0.125f));
    }

    float O[2][8][4] = {};
    float mrow[2][2], lrow[2][2];
#pragma unroll
    for (int mt = 0; mt < 2; mt++)
        for (int p = 0; p < 2; p++) { mrow[mt][p] = -1e30f; lrow[mt][p] = 0.0f; }

    const int ntiles = 2 * qt + 34;
    const int mstart = 2 * qt + 32;

    for (int kt = 0; kt < ntiles; kt++) {
        const int j0 = kt << 6;
        __syncthreads();                   // prev-iter readers of Ks/Vs done
#pragma unroll
        for (int it = 0; it < 8; it++) {
            int fid = it * 128 + tid;      // float4 index 0..1023
            int j = fid >> 4, d0 = (fid & 15) << 2;
            float4 kv = *(const float4*)&Kb[(size_t)(j0 + j) * 64 + d0];
            *(uint4*)&Ks[j * 68 + d0] = make_uint4(f2tf(kv.x), f2tf(kv.y), f2tf(kv.z), f2tf(kv.w));
            float4 vv = *(const float4*)&Vb[(size_t)(j0 + j) * 64 + d0];
            *(uint4*)&Vs[j * 72 + d0] = make_uint4(f2tf(vv.x), f2tf(vv.y), f2tf(vv.z), f2tf(vv.w));
        }
        __syncthreads();

        // ---- S = Q K^T (scores already scaled via Q) ----
        float S[2][8][4] = {};
#pragma unroll
        for (int ks = 0; ks < 8; ks++) {
            unsigned af[2][4];
#pragma unroll
            for (int mt = 0; mt < 2; mt++) {
                int rb = rbw + mt * 16;
                af[mt][0] = Qs[(rb + gi)     * 68 + ks * 8 + ti];
                af[mt][1] = Qs[(rb + gi + 8) * 68 + ks * 8 + ti];
                af[mt][2] = Qs[(rb + gi)     * 68 + ks * 8 + ti + 4];
                af[mt][3] = Qs[(rb + gi + 8) * 68 + ks * 8 + ti + 4];
            }
#pragma unroll
            for (int nt = 0; nt < 8; nt++) {
                unsigned b0 = Ks[(nt * 8 + gi) * 68 + ks * 8 + ti];
                unsigned b1 = Ks[(nt * 8 + gi) * 68 + ks * 8 + ti + 4];
                mma8(S[0][nt], af[0], b0, b1);
                mma8(S[1][nt], af[1], b0, b1);
            }
        }

        // ---- causal mask (last two tiles only) ----
        if (kt >= mstart) {
#pragma unroll
            for (int mt = 0; mt < 2; mt++)
#pragma unroll
                for (int p = 0; p < 2; p++) {
                    int i = i0 + rbw + mt * 16 + gi + p * 8;
#pragma unroll
                    for (int nt = 0; nt < 8; nt++) {
                        int j = j0 + nt * 8 + 2 * ti;
                        if (j     > i + TCACHE) S[mt][nt][2 * p]     = -1e30f;
                        if (j + 1 > i + TCACHE) S[mt][nt][2 * p + 1] = -1e30f;
                    }
                }
        }

        // ---- online softmax on fragments (quad-lane reductions) ----
        float alpha[2][2];
#pragma unroll
        for (int mt = 0; mt < 2; mt++)
#pragma unroll
            for (int p = 0; p < 2; p++) {
                float mx = -1e30f;
#pragma unroll
                for (int nt = 0; nt < 8; nt++)
                    mx = fmaxf(mx, fmaxf(S[mt][nt][2 * p], S[mt][nt][2 * p + 1]));
                mx = fmaxf(mx, __shfl_xor_sync(0xffffffffu, mx, 1));
                mx = fmaxf(mx, __shfl_xor_sync(0xffffffffu, mx, 2));
                float mn = fmaxf(mrow[mt][p], mx);
                alpha[mt][p] = __expf(mrow[mt][p] - mn);
                mrow[mt][p] = mn;
                float ls = 0.0f;
#pragma unroll
                for (int nt = 0; nt < 8; nt++) {
                    float e0 = __expf(S[mt][nt][2 * p]     - mn);
                    float e1 = __expf(S[mt][nt][2 * p + 1] - mn);
                    S[mt][nt][2 * p] = e0;
                    S[mt][nt][2 * p + 1] = e1;
                    ls += e0 + e1;
                }
                ls += __shfl_xor_sync(0xffffffffu, ls, 1);
                ls += __shfl_xor_sync(0xffffffffu, ls, 2);
                lrow[mt][p] = lrow[mt][p] * alpha[mt][p] + ls;
            }

        // ---- write P to smem (tf32), rescale O ----
#pragma unroll
        for (int mt = 0; mt < 2; mt++) {
            int r1 = rbw + mt * 16 + gi;
#pragma unroll
            for (int nt = 0; nt < 8; nt++) {
                *(uint2*)&Ps[r1 * 68 + nt * 8 + 2 * ti] =
                    make_uint2(f2tf(S[mt][nt][0]), f2tf(S[mt][nt][1]));
                *(uint2*)&Ps[(r1 + 8) * 68 + nt * 8 + 2 * ti] =
                    make_uint2(f2tf(S[mt][nt][2]), f2tf(S[mt][nt][3]));
                O[mt][nt][0] *= alpha[mt][0];
                O[mt][nt][1] *= alpha[mt][0];
                O[mt][nt][2] *= alpha[mt][1];
                O[mt][nt][3] *= alpha[mt][1];
            }
        }
        __syncwarp();                      // Ps rows produced+consumed within warp

        // ---- O += P V ----
#pragma unroll
        for (int ks = 0; ks < 8; ks++) {
            unsigned af[2][4];
#pragma unroll
            for (int mt = 0; mt < 2; mt++) {
                int rb = rbw + mt * 16;
                af[mt][0] = Ps[(rb + gi)     * 68 + ks * 8 + ti];
                af[mt][1] = Ps[(rb + gi + 8) * 68 + ks * 8 + ti];
                af[mt][2] = Ps[(rb + gi)     * 68 + ks * 8 + ti + 4];
                af[mt][3] = Ps[(rb + gi + 8) * 68 + ks * 8 + ti + 4];
            }
#pragma unroll
            for (int nt = 0; nt < 8; nt++) {
                unsigned b0 = Vs[(ks * 8 + ti)     * 72 + nt * 8 + gi];
                unsigned b1 = Vs[(ks * 8 + ti + 4) * 72 + nt * 8 + gi];
                mma8(O[0][nt], af[0], b0, b1);
                mma8(O[1][nt], af[1], b0, b1);
            }
        }
    }

    // ---- epilogue: normalize + write g_att [b,t,h,d] ----
    const int b = bh >> 4, h = bh & 15;
#pragma unroll
    for (int mt = 0; mt < 2; mt++) {
        float inv0 = 1.0f / lrow[mt][0];
        float inv1 = 1.0f / lrow[mt][1];
        int r1 = i0 + rbw + mt * 16 + gi;
#pragma unroll
        for (int nt = 0; nt < 8; nt++) {
            int d = nt * 8 + 2 * ti;
            *(float2*)&g_att[((size_t)(b * TQ + r1) * N_HEADS + h) * HEAD_DIM + d] =
                make_float2(O[mt][nt][0] * inv0, O[mt][nt][1] * inv0);
            *(float2*)&g_att[((size_t)(b * TQ + r1 + 8) * N_HEADS + h) * HEAD_DIM + d] =
                make_float2(O[mt][nt][2] * inv1, O[mt][nt][3] * inv1);
        }
    }
}

// ---------------------------------------------------------------------------
extern "C" void kernel_launch(void* const* d_in, const int* in_sizes, int n_in,
                              void* d_out, int out_size) {
    (void)in_sizes; (void)n_in; (void)out_size;
    const float* x  = (const float*)d_in[0];
    const float* kc = (const float*)d_in[1];
    const float* vc = (const float*)d_in[2];
    const float* Wq = (const float*)d_in[3];
    const float* bq = (const float*)d_in[4];
    const float* Wk = (const float*)d_in[5];
    const float* bk = (const float*)d_in[6];
    const float* Wv = (const float*)d_in[7];
    const float* bv = (const float*)d_in[8];
    const float* Wo = (const float*)d_in[9];
    const float* bo = (const float*)d_in[10];

    float* out   = (float*)d_out;
    float* k_out = out + OUT_ELEMS;
    float* v_out = k_out + KV_ELEMS;

    copy_cache_kernel<<<4096, 256>>>((const float4*)kc, (const float4*)vc,
                                     (float4*)k_out, (float4*)v_out);

    // Fused QKV projections
    qkv_kernel<<<dim3(8, 32, 3), 256>>>(x, Wq, bq, Wk, bk, Wv, bv, k_out, v_out);

    // Flash attention (tensor-core tf32)
    cudaFuncSetAttribute(attn_kernel, cudaFuncAttributeMaxDynamicSharedMemorySize,
                         AT_SMEM_BYTES);
    attn_kernel<<<dim3(TQ / 128, BATCH * N_HEADS), 128, AT_SMEM_BYTES>>>(k_out, v_out);

    // Output projection
    oproj_kernel<<<dim3(8, 32), 256>>>(Wo, bo, out);
}